// round 8
// baseline (speedup 1.0000x reference)
#include <cuda_runtime.h>
#include <math.h>
#include <stdint.h>

#define HIDDEN 2048
#define SEQ    1024
#define BATCH  2
#define NHEADS 32
#define NGROUP 8
#define HDIM   64
#define MTOT   (BATCH * SEQ)
#define KVW    (NGROUP * HDIM)   /* 512 */
#define QKVW   (HIDDEN + 2 * KVW) /* 3072 */

/* ---------------- scratch (no cudaMalloc allowed) ---------------- */
__device__ float g_xt [MTOT * HIDDEN];               /* tf32 bits of x */
__device__ float g_wt [QKVW * HIDDEN];               /* Wq|Wk|Wv tf32  */
__device__ float g_wot[HIDDEN * HIDDEN];             /* Wo tf32        */
__device__ float g_q  [MTOT * HIDDEN];
__device__ float g_k  [MTOT * KVW];
__device__ float g_v  [MTOT * KVW];
__device__ float g_attn[MTOT * HIDDEN];              /* tf32 bits      */
__device__ float g_qkvp[2 * MTOT * QKVW];            /* split-K partials */
__device__ float g_op  [2 * MTOT * HIDDEN];

/* ---------------- helpers ---------------- */
__device__ __forceinline__ uint32_t f2tf32(float x) {
    uint32_t r;
    asm("cvt.rna.tf32.f32 %0, %1;" : "=r"(r) : "f"(x));
    return r;
}
__device__ __forceinline__ uint32_t smem_u32(const void* p) {
    uint32_t a;
    asm("{ .reg .u64 t; cvta.to.shared.u64 t, %1; cvt.u32.u64 %0, t; }"
        : "=r"(a) : "l"(p));
    return a;
}
__device__ __forceinline__ void mma_tf32(float* c, const uint32_t* a,
                                         uint32_t b0, uint32_t b1) {
    asm volatile(
        "mma.sync.aligned.m16n8k8.row.col.f32.tf32.tf32.f32 "
        "{%0,%1,%2,%3}, {%4,%5,%6,%7}, {%8,%9}, {%0,%1,%2,%3};"
        : "+f"(c[0]), "+f"(c[1]), "+f"(c[2]), "+f"(c[3])
        : "r"(a[0]), "r"(a[1]), "r"(a[2]), "r"(a[3]), "r"(b0), "r"(b1));
}
__device__ __forceinline__ void ldsm_x4(uint32_t* r, uint32_t addr) {
    asm volatile("ldmatrix.sync.aligned.m8n8.x4.shared.b16 {%0,%1,%2,%3}, [%4];"
        : "=r"(r[0]), "=r"(r[1]), "=r"(r[2]), "=r"(r[3]) : "r"(addr));
}
__device__ __forceinline__ void cp16(uint32_t dst, const void* src) {
    asm volatile("cp.async.cg.shared.global [%0], [%1], 16;"
                 :: "r"(dst), "l"(src));
}
#define CP_COMMIT() asm volatile("cp.async.commit_group;" ::: "memory")
#define CP_WAIT0()  asm volatile("cp.async.wait_group 0;"  ::: "memory")

/* =================================================================
 * Pre-convert x, Wq|Wk|Wv, Wo to tf32 bits (grid-stride, float4).
 * ================================================================= */
__global__ void cvt_all(const float4* __restrict__ x,
                        const float4* __restrict__ wq,
                        const float4* __restrict__ wk,
                        const float4* __restrict__ wv,
                        const float4* __restrict__ wo)
{
    const int64_t N0 = 1048576;
    const int64_t N1 = N0 + 1048576;
    const int64_t N2 = N1 + 262144;
    const int64_t N3 = N2 + 262144;
    const int64_t N4 = N3 + 1048576;
    uint4* xt  = (uint4*)g_xt;
    uint4* wt  = (uint4*)g_wt;
    uint4* wot = (uint4*)g_wot;
    for (int64_t i = (int64_t)blockIdx.x * blockDim.x + threadIdx.x;
         i < N4; i += (int64_t)gridDim.x * blockDim.x) {
        float4 v; uint4* dst;
        if (i < N0)      { v = x [i];      dst = xt  + i; }
        else if (i < N1) { v = wq[i - N0]; dst = wt  + (i - N0); }
        else if (i < N2) { v = wk[i - N1]; dst = wt  + 1048576 + (i - N1); }
        else if (i < N3) { v = wv[i - N2]; dst = wt  + 1310720 + (i - N2); }
        else             { v = wo[i - N3]; dst = wot + (i - N3); }
        uint4 u;
        u.x = f2tf32(v.x); u.y = f2tf32(v.y);
        u.z = f2tf32(v.z); u.w = f2tf32(v.w);
        *dst = u;
    }
}

/* =================================================================
 * TF32 NT GEMM, split-K partial: P[m,n] = sum_{k in half} A[m,k]*B[n,k]
 * CTA 128x128, 128 threads (4 warps 2x2), warp tile 64x64, BK=32,
 * cp.async double-buffered, XOR-swizzled 128B smem rows.
 * ================================================================= */
#define BK    32
#define TILEB 16384
#define STAGE (2 * TILEB)
#define GEMM_SMEM (2 * STAGE)          /* 65536 */
#define KHALF (HIDDEN / 2)             /* 1024  */
#define NITER (KHALF / BK)             /* 32    */

__device__ __forceinline__ void gemm_core_sk(
    const float* __restrict__ A, const float* __restrict__ Bm,
    float* __restrict__ P, int ldp, int m0, int n0, int kOff)
{
    extern __shared__ char smem[];
    const uint32_t sb = smem_u32(smem);
    const int tid = threadIdx.x, lane = tid & 31, wid = tid >> 5;
    const int wm = (wid & 1) * 64, wn = (wid >> 1) * 64;
    const int grp = lane >> 3;

    const uint32_t xm   = (uint32_t)(lane & 7) << 4;
    const uint32_t rowA = (uint32_t)(wm + (lane & 7) + ((grp & 1) << 3)) * 128;
    const uint32_t rowB = (uint32_t)(wn + (lane & 7) + ((grp >> 1) << 3)) * 128;
    const uint32_t cA   = (uint32_t)(grp >> 1) << 4;
    const uint32_t cB   = (uint32_t)(grp & 1) << 4;

    float acc[4][8][4];
#pragma unroll
    for (int mt = 0; mt < 4; mt++)
#pragma unroll
        for (int nt = 0; nt < 8; nt++) {
            acc[mt][nt][0] = 0.f; acc[mt][nt][1] = 0.f;
            acc[mt][nt][2] = 0.f; acc[mt][nt][3] = 0.f;
        }

    const float* Ag = A  + (size_t)(m0 + tid) * HIDDEN + kOff;
    const float* Bg = Bm + (size_t)(n0 + tid) * HIDDEN + kOff;
    const uint32_t sRow = (uint32_t)tid * 128;
    const uint32_t sX   = (uint32_t)(tid & 7) << 4;

    /* prologue: stage 0 */
#pragma unroll
    for (int i = 0; i < 8; i++) {
        const uint32_t d = sRow + (((uint32_t)i << 4) ^ sX);
        cp16(sb + d,         Ag + i * 4);
        cp16(sb + TILEB + d, Bg + i * 4);
    }
    CP_COMMIT();

    for (int it = 0; it < NITER; it++) {
        CP_WAIT0();
        __syncthreads();

        const uint32_t aB = sb + (it & 1) * STAGE;
        const uint32_t bB = aB + TILEB;
        const uint32_t nx = sb + ((it + 1) & 1) * STAGE;
        const bool pf = (it + 1 < NITER);
        const float* Ap = Ag + (it + 1) * BK;
        const float* Bp = Bg + (it + 1) * BK;

#pragma unroll
        for (int ks = 0; ks < 4; ks++) {
            if (pf) {
                const uint32_t d0 = sRow + ((((uint32_t)(2 * ks) << 4))     ^ sX);
                const uint32_t d1 = sRow + ((((uint32_t)(2 * ks + 1) << 4)) ^ sX);
                cp16(nx + d0,         Ap + (2 * ks) * 4);
                cp16(nx + d1,         Ap + (2 * ks + 1) * 4);
                cp16(nx + TILEB + d0, Bp + (2 * ks) * 4);
                cp16(nx + TILEB + d1, Bp + (2 * ks + 1) * 4);
            }
            const uint32_t ck = ((uint32_t)ks << 5);
            uint32_t af[4][4];
#pragma unroll
            for (int mt = 0; mt < 4; mt++)
                ldsm_x4(af[mt], aB + rowA + mt * 2048 + ((ck + cA) ^ xm));
            uint32_t bf[2][4];
            ldsm_x4(bf[0], bB + rowB + ((ck + cB) ^ xm));
#pragma unroll
            for (int nt2 = 0; nt2 < 4; nt2++) {
                const int c = nt2 & 1, n = 1 - c;
                if (nt2 < 3)
                    ldsm_x4(bf[n], bB + rowB + (nt2 + 1) * 2048 + ((ck + cB) ^ xm));
#pragma unroll
                for (int mt = 0; mt < 4; mt++) {
                    mma_tf32(acc[mt][2 * nt2],     af[mt], bf[c][0], bf[c][1]);
                    mma_tf32(acc[mt][2 * nt2 + 1], af[mt], bf[c][2], bf[c][3]);
                }
            }
        }
        CP_COMMIT();
    }

    /* epilogue: plain partial stores */
    const int r0 = lane >> 2, a4 = lane & 3;
#pragma unroll
    for (int mt = 0; mt < 4; mt++) {
#pragma unroll
        for (int nt = 0; nt < 8; nt++) {
            const int col = n0 + wn + nt * 8 + 2 * a4;
            const int rA = m0 + wm + mt * 16 + r0;
            *(float2*)&P[(size_t)rA * ldp + col] =
                make_float2(acc[mt][nt][0], acc[mt][nt][1]);
            *(float2*)&P[(size_t)(rA + 8) * ldp + col] =
                make_float2(acc[mt][nt][2], acc[mt][nt][3]);
        }
    }
}

/* fused QKV projection, split-K: grid (24, 16, 2) */
__global__ __launch_bounds__(128, 3) void qkv_sk()
{
    const int z = blockIdx.z;
    gemm_core_sk(g_xt, g_wt,
                 g_qkvp + (size_t)z * MTOT * QKVW, QKVW,
                 blockIdx.y * 128, blockIdx.x * 128, z * KHALF);
}

/* O projection, split-K: grid (16, 16, 2) */
__global__ __launch_bounds__(128, 3) void oproj_sk()
{
    const int z = blockIdx.z;
    gemm_core_sk(g_attn, g_wot,
                 g_op + (size_t)z * MTOT * HIDDEN, HIDDEN,
                 blockIdx.y * 128, blockIdx.x * 128, z * KHALF);
}

/* reduce qkv partials: out = p0 + p1 + bias, scatter to g_q/g_k/g_v */
__global__ void reduce_qkv(const float* __restrict__ bq,
                           const float* __restrict__ bk,
                           const float* __restrict__ bv)
{
    const float4* p0 = (const float4*)g_qkvp;
    const float4* p1 = (const float4*)(g_qkvp + (size_t)MTOT * QKVW);
    const int64_t N = (int64_t)MTOT * QKVW / 4;
    for (int64_t i = (int64_t)blockIdx.x * blockDim.x + threadIdx.x;
         i < N; i += (int64_t)gridDim.x * blockDim.x) {
        const int col = (int)((i * 4) % QKVW);
        const int row = (int)((i * 4) / QKVW);
        float4 a = p0[i], b = p1[i];
        const float* bias; float* dst;
        if (col < HIDDEN)      { bias = bq + col;        dst = g_q + (size_t)row * HIDDEN + col; }
        else if (col < 2560)   { bias = bk + col - 2048; dst = g_k + (size_t)row * KVW + col - 2048; }
        else                   { bias = bv + col - 2560; dst = g_v + (size_t)row * KVW + col - 2560; }
        float4 r;
        r.x = a.x + b.x + bias[0];
        r.y = a.y + b.y + bias[1];
        r.z = a.z + b.z + bias[2];
        r.w = a.w + b.w + bias[3];
        *(float4*)dst = r;
    }
}

/* reduce O partials: out = p0 + p1 + bo */
__global__ void reduce_o(const float* __restrict__ bo, float4* __restrict__ out)
{
    const float4* p0 = (const float4*)g_op;
    const float4* p1 = (const float4*)(g_op + (size_t)MTOT * HIDDEN);
    const float4* bb = (const float4*)bo;
    const int64_t N = (int64_t)MTOT * HIDDEN / 4;
    for (int64_t i = (int64_t)blockIdx.x * blockDim.x + threadIdx.x;
         i < N; i += (int64_t)gridDim.x * blockDim.x) {
        float4 a = p0[i], b = p1[i], c = bb[(i * 4 % HIDDEN) / 4];
        float4 r;
        r.x = a.x + b.x + c.x;
        r.y = a.y + b.y + c.y;
        r.z = a.z + b.z + c.z;
        r.w = a.w + b.w + c.w;
        out[i] = r;
    }
}

/* =================================================================
 * Flash attention (causal, GQA): 128 q-rows per CTA, 256 threads
 * (8 warps x 16 rows), 64-col K tiles, mma.sync tf32 + ldmatrix.
 * ================================================================= */
#define ATS 68
#define ATT_SMEM (3 * 64 * ATS * 4)   /* 52224 B */

__global__ __launch_bounds__(256, 2) void attn_tc(
    const float* __restrict__ Q, const float* __restrict__ Kp,
    const float* __restrict__ Vp, float* __restrict__ Out)
{
    extern __shared__ uint32_t sm[];
    uint32_t* Ks = sm;
    uint32_t* Vt = sm + 2 * 64 * ATS;

    const int qt = (int)gridDim.x - 1 - (int)blockIdx.x;
    const int h = blockIdx.y, b = blockIdx.z, g = h >> 2;
    const int tid = threadIdx.x, lane = tid & 31, w = tid >> 5;
    const int r0 = lane >> 2, a4 = lane & 3;

    const int grp = lane >> 3;
    const uint32_t paOff = (uint32_t)(w * 16 + (lane & 7) + ((grp & 1) << 3)) * 272
                         + (uint32_t)(grp >> 1) * 16;
    const uint32_t bfOff = (uint32_t)((lane & 7) + ((grp >> 1) << 3)) * 272
                         + (uint32_t)(grp & 1) * 16;
    const uint32_t ksBase = smem_u32(sm);
    const uint32_t vtBase = ksBase + 2 * 64 * ATS * 4;

    uint32_t qf[8][4];
    {
        const float sc = 0.125f;
        const float* qp = Q + (size_t)(b * SEQ + qt * 128 + w * 16) * HIDDEN + h * HDIM;
#pragma unroll
        for (int ks = 0; ks < 8; ks++) {
            const int c = ks * 8 + a4;
            qf[ks][0] = f2tf32(qp[(size_t)r0 * HIDDEN + c] * sc);
            qf[ks][1] = f2tf32(qp[(size_t)(r0 + 8) * HIDDEN + c] * sc);
            qf[ks][2] = f2tf32(qp[(size_t)r0 * HIDDEN + c + 4] * sc);
            qf[ks][3] = f2tf32(qp[(size_t)(r0 + 8) * HIDDEN + c + 4] * sc);
        }
    }

    float o[8][4];
#pragma unroll
    for (int nt = 0; nt < 8; nt++) {
        o[nt][0] = 0.f; o[nt][1] = 0.f; o[nt][2] = 0.f; o[nt][3] = 0.f;
    }
    float mi0 = -1e30f, mi1 = -1e30f, l0 = 0.f, l1 = 0.f;

    const int lrow = tid >> 2;
    const int lcb  = (tid & 3) * 16;
    const int ktEnd = 2 * qt + 1;

    for (int kt = 0; kt <= ktEnd; kt++) {
        __syncthreads();

        {
            const size_t base = (size_t)(b * SEQ + kt * 64 + lrow) * KVW + g * HDIM + lcb;
            const float* kp = Kp + base;
            const float* vp = Vp + base;
#pragma unroll
            for (int u = 0; u < 4; u++) {
                float4 kv = *(const float4*)(kp + u * 4);
                uint32_t* kd = &Ks[lrow * ATS + lcb + u * 4];
                kd[0] = f2tf32(kv.x); kd[1] = f2tf32(kv.y);
                kd[2] = f2tf32(kv.z); kd[3] = f2tf32(kv.w);
                float4 vv = *(const float4*)(vp + u * 4);
                const int c = lcb + u * 4;
                Vt[(c + 0) * ATS + lrow] = f2tf32(vv.x);
                Vt[(c + 1) * ATS + lrow] = f2tf32(vv.y);
                Vt[(c + 2) * ATS + lrow] = f2tf32(vv.z);
                Vt[(c + 3) * ATS + lrow] = f2tf32(vv.w);
            }
        }
        __syncthreads();

        float s[8][4];
#pragma unroll
        for (int nt = 0; nt < 8; nt++) {
            s[nt][0] = 0.f; s[nt][1] = 0.f; s[nt][2] = 0.f; s[nt][3] = 0.f;
        }
#pragma unroll
        for (int ks = 0; ks < 8; ks++) {
#pragma unroll
            for (int nt2 = 0; nt2 < 4; nt2++) {
                uint32_t bf[4];
                ldsm_x4(bf, ksBase + bfOff + nt2 * 4352 + ks * 32);
                mma_tf32(s[2 * nt2],     qf[ks], bf[0], bf[1]);
                mma_tf32(s[2 * nt2 + 1], qf[ks], bf[2], bf[3]);
            }
        }

        if (kt >= 2 * qt) {
            const int diff  = (kt - 2 * qt) * 64;
            const int row0g = w * 16 + r0, row1g = row0g + 8;
#pragma unroll
            for (int nt = 0; nt < 8; nt++) {
                const int c0 = nt * 8 + 2 * a4 + diff, c1 = c0 + 1;
                if (c0 > row0g) s[nt][0] = -1e30f;
                if (c1 > row0g) s[nt][1] = -1e30f;
                if (c0 > row1g) s[nt][2] = -1e30f;
                if (c1 > row1g) s[nt][3] = -1e30f;
            }
        }

        float mx0 = -1e30f, mx1 = -1e30f;
#pragma unroll
        for (int nt = 0; nt < 8; nt++) {
            mx0 = fmaxf(mx0, fmaxf(s[nt][0], s[nt][1]));
            mx1 = fmaxf(mx1, fmaxf(s[nt][2], s[nt][3]));
        }
        mx0 = fmaxf(mx0, __shfl_xor_sync(0xffffffffu, mx0, 1));
        mx0 = fmaxf(mx0, __shfl_xor_sync(0xffffffffu, mx0, 2));
        mx1 = fmaxf(mx1, __shfl_xor_sync(0xffffffffu, mx1, 1));
        mx1 = fmaxf(mx1, __shfl_xor_sync(0xffffffffu, mx1, 2));
        const float nm0 = fmaxf(mi0, mx0), nm1 = fmaxf(mi1, mx1);
        const float cr0 = __expf(mi0 - nm0), cr1 = __expf(mi1 - nm1);
        float sum0 = 0.f, sum1 = 0.f;
#pragma unroll
        for (int nt = 0; nt < 8; nt++) {
            s[nt][0] = __expf(s[nt][0] - nm0);
            s[nt][1] = __expf(s[nt][1] - nm0);
            s[nt][2] = __expf(s[nt][2] - nm1);
            s[nt][3] = __expf(s[nt][3] - nm1);
            sum0 += s[nt][0] + s[nt][1];
            sum1 += s[nt][2] + s[nt][3];
        }
        sum0 += __shfl_xor_sync(0xffffffffu, sum0, 1);
        sum0 += __shfl_xor_sync(0xffffffffu, sum0, 2);
        sum1 += __shfl_xor_sync(0xffffffffu, sum1, 1);
        sum1 += __shfl_xor_sync(0xffffffffu, sum1, 2);
        l0 = l0 * cr0 + sum0;  l1 = l1 * cr1 + sum1;
        mi0 = nm0;             mi1 = nm1;
#pragma unroll
        for (int nt = 0; nt < 8; nt++) {
            o[nt][0] *= cr0; o[nt][1] *= cr0;
            o[nt][2] *= cr1; o[nt][3] *= cr1;
        }

        __syncthreads();

        {
            const int row0 = w * 16 + r0;
#pragma unroll
            for (int nt = 0; nt < 8; nt++) {
                const int c = nt * 8 + 2 * a4;
                sm[row0 * ATS + c]           = f2tf32(s[nt][0]);
                sm[row0 * ATS + c + 1]       = f2tf32(s[nt][1]);
                sm[(row0 + 8) * ATS + c]     = f2tf32(s[nt][2]);
                sm[(row0 + 8) * ATS + c + 1] = f2tf32(s[nt][3]);
            }
        }
        __syncwarp();

#pragma unroll
        for (int ks = 0; ks < 8; ks++) {
            uint32_t pa[4];
            ldsm_x4(pa, ksBase + paOff + ks * 32);
#pragma unroll
            for (int nt2 = 0; nt2 < 4; nt2++) {
                uint32_t bf[4];
                ldsm_x4(bf, vtBase + bfOff + nt2 * 4352 + ks * 32);
                mma_tf32(o[2 * nt2],     pa, bf[0], bf[1]);
                mma_tf32(o[2 * nt2 + 1], pa, bf[2], bf[3]);
            }
        }
    }

    const float inv0 = 1.f / l0, inv1 = 1.f / l1;
    const size_t row0 = (size_t)(b * SEQ + qt * 128 + w * 16 + r0);
#pragma unroll
    for (int nt = 0; nt < 8; nt++) {
        const int col = h * HDIM + nt * 8 + 2 * a4;
        *(float2*)&Out[row0 * HIDDEN + col] = make_float2(
            __uint_as_float(f2tf32(o[nt][0] * inv0)),
            __uint_as_float(f2tf32(o[nt][1] * inv0)));
        *(float2*)&Out[(row0 + 8) * HIDDEN + col] = make_float2(
            __uint_as_float(f2tf32(o[nt][2] * inv1)),
            __uint_as_float(f2tf32(o[nt][3] * inv1)));
    }
}

/* ================================================================= */
extern "C" void kernel_launch(void* const* d_in, const int* in_sizes, int n_in,
                              void* d_out, int out_size)
{
    (void)in_sizes; (void)n_in; (void)out_size;
    const float* x  = (const float*)d_in[0];
    /* d_in[1] = causal mask, handled analytically */
    const float* Wq = (const float*)d_in[2];
    const float* bq = (const float*)d_in[3];
    const float* Wk = (const float*)d_in[4];
    const float* bk = (const float*)d_in[5];
    const float* Wv = (const float*)d_in[6];
    const float* bv = (const float*)d_in[7];
    const float* Wo = (const float*)d_in[8];
    const float* bo = (const float*)d_in[9];
    float* out = (float*)d_out;

    float *q, *k, *v, *attn;
    cudaGetSymbolAddress((void**)&q,    g_q);
    cudaGetSymbolAddress((void**)&k,    g_k);
    cudaGetSymbolAddress((void**)&v,    g_v);
    cudaGetSymbolAddress((void**)&attn, g_attn);

    cudaFuncSetAttribute(qkv_sk,   cudaFuncAttributeMaxDynamicSharedMemorySize, GEMM_SMEM);
    cudaFuncSetAttribute(oproj_sk, cudaFuncAttributeMaxDynamicSharedMemorySize, GEMM_SMEM);
    cudaFuncSetAttribute(attn_tc,  cudaFuncAttributeMaxDynamicSharedMemorySize, ATT_SMEM);

    /* 1. convert inputs to tf32 bits */
    cvt_all<<<2048, 256>>>((const float4*)x, (const float4*)Wq,
                           (const float4*)Wk, (const float4*)Wv,
                           (const float4*)Wo);

    /* 2. fused Q/K/V projection (split-K=2) + reduce */
    qkv_sk<<<dim3(24, 16, 2), 128, GEMM_SMEM>>>();
    reduce_qkv<<<6144, 256>>>(bq, bk, bv);

    /* 3. causal GQA attention */
    attn_tc<<<dim3(SEQ / 128, NHEADS, BATCH), 256, ATT_SMEM>>>(q, k, v, attn);

    /* 4. output projection (split-K=2) + reduce */
    oproj_sk<<<dim3(16, 16, 2), 128, GEMM_SMEM>>>();
    reduce_o<<<4096, 256>>>(bo, (float4*)out);
}

// round 9
// speedup vs baseline: 1.1037x; 1.1037x over previous
#include <cuda_runtime.h>
#include <math.h>
#include <stdint.h>

#define HIDDEN 2048
#define SEQ    1024
#define BATCH  2
#define NHEADS 32
#define NGROUP 8
#define HDIM   64
#define MTOT   (BATCH * SEQ)
#define KVW    (NGROUP * HDIM)    /* 512  */
#define QKVW   (HIDDEN + 2 * KVW) /* 3072 */

/* ---------------- scratch (no cudaMalloc allowed) ---------------- */
__device__ float g_xt [MTOT * HIDDEN];               /* tf32 bits of x */
__device__ float g_wt [QKVW * HIDDEN];               /* Wq|Wk|Wv tf32  */
__device__ float g_wot[HIDDEN * HIDDEN];             /* Wo tf32        */
__device__ float g_q  [MTOT * HIDDEN];               /* fp32           */
__device__ float g_k  [MTOT * KVW];                  /* tf32 bits      */
__device__ float g_vt [BATCH * NGROUP * HDIM * SEQ]; /* tf32, [b,g,d,s]*/
__device__ float g_attn[MTOT * HIDDEN];              /* tf32 bits      */

/* ---------------- helpers ---------------- */
__device__ __forceinline__ uint32_t f2tf32(float x) {
    uint32_t r;
    asm("cvt.rna.tf32.f32 %0, %1;" : "=r"(r) : "f"(x));
    return r;
}
__device__ __forceinline__ uint32_t smem_u32(const void* p) {
    uint32_t a;
    asm("{ .reg .u64 t; cvta.to.shared.u64 t, %1; cvt.u32.u64 %0, t; }"
        : "=r"(a) : "l"(p));
    return a;
}
__device__ __forceinline__ void mma_tf32(float* c, const uint32_t* a,
                                         uint32_t b0, uint32_t b1) {
    asm volatile(
        "mma.sync.aligned.m16n8k8.row.col.f32.tf32.tf32.f32 "
        "{%0,%1,%2,%3}, {%4,%5,%6,%7}, {%8,%9}, {%0,%1,%2,%3};"
        : "+f"(c[0]), "+f"(c[1]), "+f"(c[2]), "+f"(c[3])
        : "r"(a[0]), "r"(a[1]), "r"(a[2]), "r"(a[3]), "r"(b0), "r"(b1));
}
__device__ __forceinline__ void ldsm_x4(uint32_t* r, uint32_t addr) {
    asm volatile("ldmatrix.sync.aligned.m8n8.x4.shared.b16 {%0,%1,%2,%3}, [%4];"
        : "=r"(r[0]), "=r"(r[1]), "=r"(r[2]), "=r"(r[3]) : "r"(addr));
}
__device__ __forceinline__ void cp16(uint32_t dst, const void* src) {
    asm volatile("cp.async.cg.shared.global [%0], [%1], 16;"
                 :: "r"(dst), "l"(src));
}
#define CP_COMMIT() asm volatile("cp.async.commit_group;" ::: "memory")
#define CP_WAIT0()  asm volatile("cp.async.wait_group 0;"  ::: "memory")
#define CP_WAIT1()  asm volatile("cp.async.wait_group 1;"  ::: "memory")

/* =================================================================
 * Pre-convert x, Wq|Wk|Wv, Wo to tf32 bits (grid-stride, float4).
 * ================================================================= */
__global__ void cvt_all(const float4* __restrict__ x,
                        const float4* __restrict__ wq,
                        const float4* __restrict__ wk,
                        const float4* __restrict__ wv,
                        const float4* __restrict__ wo)
{
    const int64_t N0 = 1048576;
    const int64_t N1 = N0 + 1048576;
    const int64_t N2 = N1 + 262144;
    const int64_t N3 = N2 + 262144;
    const int64_t N4 = N3 + 1048576;
    uint4* xt  = (uint4*)g_xt;
    uint4* wt  = (uint4*)g_wt;
    uint4* wot = (uint4*)g_wot;
    for (int64_t i = (int64_t)blockIdx.x * blockDim.x + threadIdx.x;
         i < N4; i += (int64_t)gridDim.x * blockDim.x) {
        float4 v; uint4* dst;
        if (i < N0)      { v = x [i];      dst = xt  + i; }
        else if (i < N1) { v = wq[i - N0]; dst = wt  + (i - N0); }
        else if (i < N2) { v = wk[i - N1]; dst = wt  + 1048576 + (i - N1); }
        else if (i < N3) { v = wv[i - N2]; dst = wt  + 1310720 + (i - N2); }
        else             { v = wo[i - N3]; dst = wot + (i - N3); }
        uint4 u;
        u.x = f2tf32(v.x); u.y = f2tf32(v.y);
        u.z = f2tf32(v.z); u.w = f2tf32(v.w);
        *dst = u;
    }
}

/* =================================================================
 * TF32 NT GEMM (R7 core), cp.async double-buffered, BK=32,
 * XOR-swizzled 128B rows. CTA 128x128, 4 warps (2x2), warp 64x64.
 * MODE epilogues: 0 = fp32+bias, 1 = tf32+bias, 2 = tf32+bias
 * transposed into g_vt.
 * ================================================================= */
#define BK    32
#define TILEB 16384
#define STAGE (2 * TILEB)
#define GEMM_SMEM (2 * STAGE)          /* 65536 */

template<int MODE>
__device__ __forceinline__ void gemm_core(
    const float* __restrict__ A, const float* __restrict__ Bm,
    const float* __restrict__ bias, float* __restrict__ C,
    int ldc, int K, int m0, int n0B, int n0C)
{
    extern __shared__ char smem[];
    const uint32_t sb = smem_u32(smem);
    const int tid = threadIdx.x, lane = tid & 31, wid = tid >> 5;
    const int wm = (wid & 1) * 64, wn = (wid >> 1) * 64;
    const int grp = lane >> 3;

    const uint32_t xm   = (uint32_t)(lane & 7) << 4;
    const uint32_t rowA = (uint32_t)(wm + (lane & 7) + ((grp & 1) << 3)) * 128;
    const uint32_t rowB = (uint32_t)(wn + (lane & 7) + ((grp >> 1) << 3)) * 128;
    const uint32_t cA   = (uint32_t)(grp >> 1) << 4;
    const uint32_t cB   = (uint32_t)(grp & 1) << 4;

    float acc[4][8][4];
#pragma unroll
    for (int mt = 0; mt < 4; mt++)
#pragma unroll
        for (int nt = 0; nt < 8; nt++) {
            acc[mt][nt][0] = 0.f; acc[mt][nt][1] = 0.f;
            acc[mt][nt][2] = 0.f; acc[mt][nt][3] = 0.f;
        }

    const float* Ag = A  + (size_t)(m0  + tid) * K;
    const float* Bg = Bm + (size_t)(n0B + tid) * K;
    const uint32_t sRow = (uint32_t)tid * 128;
    const uint32_t sX   = (uint32_t)(tid & 7) << 4;
    const int nIter = K / BK;

#pragma unroll
    for (int i = 0; i < 8; i++) {
        const uint32_t d = sRow + (((uint32_t)i << 4) ^ sX);
        cp16(sb + d,         Ag + i * 4);
        cp16(sb + TILEB + d, Bg + i * 4);
    }
    CP_COMMIT();

    for (int it = 0; it < nIter; it++) {
        CP_WAIT0();
        __syncthreads();

        const uint32_t aB = sb + (it & 1) * STAGE;
        const uint32_t bB = aB + TILEB;
        const uint32_t nx = sb + ((it + 1) & 1) * STAGE;
        const bool pf = (it + 1 < nIter);
        const float* Ap = Ag + (it + 1) * BK;
        const float* Bp = Bg + (it + 1) * BK;

#pragma unroll
        for (int ks = 0; ks < 4; ks++) {
            if (pf) {
                const uint32_t d0 = sRow + ((((uint32_t)(2 * ks) << 4))     ^ sX);
                const uint32_t d1 = sRow + ((((uint32_t)(2 * ks + 1) << 4)) ^ sX);
                cp16(nx + d0,         Ap + (2 * ks) * 4);
                cp16(nx + d1,         Ap + (2 * ks + 1) * 4);
                cp16(nx + TILEB + d0, Bp + (2 * ks) * 4);
                cp16(nx + TILEB + d1, Bp + (2 * ks + 1) * 4);
            }
            const uint32_t ck = ((uint32_t)ks << 5);
            uint32_t af[4][4];
#pragma unroll
            for (int mt = 0; mt < 4; mt++)
                ldsm_x4(af[mt], aB + rowA + mt * 2048 + ((ck + cA) ^ xm));
            uint32_t bf[2][4];
            ldsm_x4(bf[0], bB + rowB + ((ck + cB) ^ xm));
#pragma unroll
            for (int nt2 = 0; nt2 < 4; nt2++) {
                const int c = nt2 & 1, n = 1 - c;
                if (nt2 < 3)
                    ldsm_x4(bf[n], bB + rowB + (nt2 + 1) * 2048 + ((ck + cB) ^ xm));
#pragma unroll
                for (int mt = 0; mt < 4; mt++) {
                    mma_tf32(acc[mt][2 * nt2],     af[mt], bf[c][0], bf[c][1]);
                    mma_tf32(acc[mt][2 * nt2 + 1], af[mt], bf[c][2], bf[c][3]);
                }
            }
        }
        CP_COMMIT();
    }

    const int r0 = lane >> 2, a4 = lane & 3;
#pragma unroll
    for (int mt = 0; mt < 4; mt++) {
#pragma unroll
        for (int nt = 0; nt < 8; nt++) {
            const int col = n0C + wn + nt * 8 + 2 * a4;
            const float b0 = bias[col], b1 = bias[col + 1];
            const int rA = m0 + wm + mt * 16 + r0;
            if (MODE == 0) {
                *(float2*)&C[(size_t)rA * ldc + col] =
                    make_float2(acc[mt][nt][0] + b0, acc[mt][nt][1] + b1);
                *(float2*)&C[(size_t)(rA + 8) * ldc + col] =
                    make_float2(acc[mt][nt][2] + b0, acc[mt][nt][3] + b1);
            } else if (MODE == 1) {
                *(float2*)&C[(size_t)rA * ldc + col] = make_float2(
                    __uint_as_float(f2tf32(acc[mt][nt][0] + b0)),
                    __uint_as_float(f2tf32(acc[mt][nt][1] + b1)));
                *(float2*)&C[(size_t)(rA + 8) * ldc + col] = make_float2(
                    __uint_as_float(f2tf32(acc[mt][nt][2] + b0)),
                    __uint_as_float(f2tf32(acc[mt][nt][3] + b1)));
            } else {
                /* transposed tf32 store into g_vt[b,g,d,s] */
                const int r1 = rA + 8;
#pragma unroll
                for (int q = 0; q < 2; q++) {
                    const int r = q ? r1 : rA;
                    const size_t base =
                        ((size_t)((r >> 10) * 8 + (col >> 6)) * 64) * 1024
                        + (size_t)(r & 1023);
                    g_vt[base + (size_t)(col & 63) * 1024] =
                        __uint_as_float(f2tf32(acc[mt][nt][2 * q] + b0));
                    g_vt[base + (size_t)((col & 63) + 1) * 1024] =
                        __uint_as_float(f2tf32(acc[mt][nt][2 * q + 1] + b1));
                }
            }
        }
    }
}

/* fused QKV projection: grid (24, 16) */
__global__ __launch_bounds__(128, 3) void qkv_gemm(
    const float* __restrict__ bq, const float* __restrict__ bk,
    const float* __restrict__ bv)
{
    const int n0 = blockIdx.x * 128, m0 = blockIdx.y * 128;
    if (n0 < 2048)
        gemm_core<0>(g_xt, g_wt, bq, g_q, HIDDEN, HIDDEN, m0, n0, n0);
    else if (n0 < 2560)
        gemm_core<1>(g_xt, g_wt, bk, g_k, KVW, HIDDEN, m0, n0, n0 - 2048);
    else
        gemm_core<2>(g_xt, g_wt, bv, (float*)0, KVW, HIDDEN, m0, n0, n0 - 2560);
}

/* O projection: grid (16, 16) */
__global__ __launch_bounds__(128, 3) void oproj_gemm(
    const float* __restrict__ bo, float* __restrict__ out)
{
    gemm_core<0>(g_attn, g_wot, bo, out, HIDDEN, HIDDEN,
                 blockIdx.y * 128, blockIdx.x * 128, blockIdx.x * 128);
}

/* =================================================================
 * Flash attention v2 (causal, GQA): 128 q-rows/CTA, 256 thr, 8 warps.
 * K (tf32) + V (tf32, pre-transposed) staged via cp.async into
 * 3-stage pipeline; XOR-swizzled 256B rows. P kept in registers via
 * lane-shuffle C-frag -> A-frag conversion. 1 barrier per KV tile.
 * ================================================================= */
#define KSTG  16384                    /* 64 rows x 256 B */
#define ASTG  (2 * KSTG)
#define ATT_SMEM (3 * ASTG)            /* 98304 */

__global__ __launch_bounds__(256, 2) void attn_tc(
    const float* __restrict__ Q, const float* __restrict__ Kp,
    const float* __restrict__ Vtg, float* __restrict__ Out)
{
    extern __shared__ char smA[];
    const uint32_t sb = smem_u32(smA);

    const int qt = (int)gridDim.x - 1 - (int)blockIdx.x;  /* longest first */
    const int h = blockIdx.y, b = blockIdx.z, g = h >> 2;
    const int tid = threadIdx.x, lane = tid & 31, w = tid >> 5;
    const int r0 = lane >> 2, a4 = lane & 3;
    const int grp = lane >> 3;

    /* cp.async source/dst for this thread */
    const int srow = tid >> 2, csel = tid & 3;
    const float* ksrc = Kp  + ((size_t)(b * SEQ) + srow) * KVW + g * HDIM + csel * 4;
    const float* vsrc = Vtg + ((size_t)((b * NGROUP + g) * HDIM + srow)) * SEQ + csel * 4;
    uint32_t dOff[4];
#pragma unroll
    for (int i = 0; i < 4; i++)
        dOff[i] = (uint32_t)srow * 256 + ((uint32_t)((4 * i + csel) ^ (srow & 7)) << 4);

    /* ldsm lane constants */
    const uint32_t rown  = (uint32_t)((lane & 7) + ((grp >> 1) << 3));
    const uint32_t rterm = rown * 256;
    const uint32_t r7    = rown & 7;
    const uint32_t cbit  = (uint32_t)(grp & 1);

    /* P shuffle constants */
    const int L0 = r0 * 4 + (a4 >> 1), L1 = L0 + 2;
    const bool pOdd = (a4 & 1) != 0;

    /* ---- hoist Q fragments (fp32 -> scaled tf32) ---- */
    uint32_t qf[8][4];
    {
        const float sc = 0.125f;
        const float* qp = Q + (size_t)(b * SEQ + qt * 128 + w * 16) * HIDDEN + h * HDIM;
#pragma unroll
        for (int kc = 0; kc < 8; kc++) {
            const int c = kc * 8 + a4;
            qf[kc][0] = f2tf32(qp[(size_t)r0 * HIDDEN + c] * sc);
            qf[kc][1] = f2tf32(qp[(size_t)(r0 + 8) * HIDDEN + c] * sc);
            qf[kc][2] = f2tf32(qp[(size_t)r0 * HIDDEN + c + 4] * sc);
            qf[kc][3] = f2tf32(qp[(size_t)(r0 + 8) * HIDDEN + c + 4] * sc);
        }
    }

    float o[8][4];
#pragma unroll
    for (int nt = 0; nt < 8; nt++) {
        o[nt][0] = 0.f; o[nt][1] = 0.f; o[nt][2] = 0.f; o[nt][3] = 0.f;
    }
    float mi0 = -1e30f, mi1 = -1e30f, l0s = 0.f, l1s = 0.f;

    const int ktEnd = 2 * qt + 1;

    /* prologue: tiles 0, 1 */
#pragma unroll
    for (int t = 0; t < 2; t++) {
        const uint32_t buf = sb + t * ASTG;
        const float* kp = ksrc + (size_t)t * 64 * KVW;
        const float* vp = vsrc + t * 64;
#pragma unroll
        for (int i = 0; i < 4; i++) {
            cp16(buf + dOff[i],        kp + i * 16);
            cp16(buf + KSTG + dOff[i], vp + i * 16);
        }
        CP_COMMIT();
    }

    int cur = 0;
    for (int kt = 0; kt <= ktEnd; kt++) {
        CP_WAIT1();
        __syncthreads();

        /* prefetch kt+2 into buffer (kt+2)%3 */
        if (kt + 2 <= ktEnd) {
            int nb = cur + 2; if (nb >= 3) nb -= 3;
            const uint32_t buf = sb + nb * ASTG;
            const float* kp = ksrc + (size_t)(kt + 2) * 64 * KVW;
            const float* vp = vsrc + (kt + 2) * 64;
#pragma unroll
            for (int i = 0; i < 4; i++) {
                cp16(buf + dOff[i],        kp + i * 16);
                cp16(buf + KSTG + dOff[i], vp + i * 16);
            }
        }
        CP_COMMIT();

        const uint32_t kbuf = sb + cur * ASTG;
        const uint32_t vbuf = kbuf + KSTG;

        /* ---- S = Q K^T ---- */
        float s[8][4];
#pragma unroll
        for (int nt = 0; nt < 8; nt++) {
            s[nt][0] = 0.f; s[nt][1] = 0.f; s[nt][2] = 0.f; s[nt][3] = 0.f;
        }
#pragma unroll
        for (int kc = 0; kc < 8; kc++) {
            const uint32_t kk = ((((uint32_t)(kc << 1)) | cbit) ^ r7) << 4;
#pragma unroll
            for (int nt2 = 0; nt2 < 4; nt2++) {
                uint32_t bf[4];
                ldsm_x4(bf, kbuf + nt2 * 4096 + rterm + kk);
                mma_tf32(s[2 * nt2],     qf[kc], bf[0], bf[1]);
                mma_tf32(s[2 * nt2 + 1], qf[kc], bf[2], bf[3]);
            }
        }

        /* ---- causal mask (diagonal-band tiles) ---- */
        if (kt >= 2 * qt) {
            const int diff  = (kt - 2 * qt) * 64;
            const int row0g = w * 16 + r0, row1g = row0g + 8;
#pragma unroll
            for (int nt = 0; nt < 8; nt++) {
                const int c0 = nt * 8 + 2 * a4 + diff, c1 = c0 + 1;
                if (c0 > row0g) s[nt][0] = -1e30f;
                if (c1 > row0g) s[nt][1] = -1e30f;
                if (c0 > row1g) s[nt][2] = -1e30f;
                if (c1 > row1g) s[nt][3] = -1e30f;
            }
        }

        /* ---- online softmax ---- */
        float mx0 = -1e30f, mx1 = -1e30f;
#pragma unroll
        for (int nt = 0; nt < 8; nt++) {
            mx0 = fmaxf(mx0, fmaxf(s[nt][0], s[nt][1]));
            mx1 = fmaxf(mx1, fmaxf(s[nt][2], s[nt][3]));
        }
        mx0 = fmaxf(mx0, __shfl_xor_sync(0xffffffffu, mx0, 1));
        mx0 = fmaxf(mx0, __shfl_xor_sync(0xffffffffu, mx0, 2));
        mx1 = fmaxf(mx1, __shfl_xor_sync(0xffffffffu, mx1, 1));
        mx1 = fmaxf(mx1, __shfl_xor_sync(0xffffffffu, mx1, 2));
        const float nm0 = fmaxf(mi0, mx0), nm1 = fmaxf(mi1, mx1);
        const float cr0 = __expf(mi0 - nm0), cr1 = __expf(mi1 - nm1);
        float sum0 = 0.f, sum1 = 0.f;
#pragma unroll
        for (int nt = 0; nt < 8; nt++) {
            s[nt][0] = __expf(s[nt][0] - nm0);
            s[nt][1] = __expf(s[nt][1] - nm0);
            s[nt][2] = __expf(s[nt][2] - nm1);
            s[nt][3] = __expf(s[nt][3] - nm1);
            sum0 += s[nt][0] + s[nt][1];
            sum1 += s[nt][2] + s[nt][3];
        }
        sum0 += __shfl_xor_sync(0xffffffffu, sum0, 1);
        sum0 += __shfl_xor_sync(0xffffffffu, sum0, 2);
        sum1 += __shfl_xor_sync(0xffffffffu, sum1, 1);
        sum1 += __shfl_xor_sync(0xffffffffu, sum1, 2);
        l0s = l0s * cr0 + sum0;  l1s = l1s * cr1 + sum1;
        mi0 = nm0;               mi1 = nm1;
#pragma unroll
        for (int nt = 0; nt < 8; nt++) {
            o[nt][0] *= cr0; o[nt][1] *= cr0;
            o[nt][2] *= cr1; o[nt][3] *= cr1;
        }

        /* ---- O += P @ V : P via register shuffles ---- */
#pragma unroll
        for (int kc = 0; kc < 8; kc++) {
            uint32_t pa[4];
            {
                float v0 = __shfl_sync(0xffffffffu, s[kc][0], L0);
                float v1 = __shfl_sync(0xffffffffu, s[kc][1], L0);
                pa[0] = f2tf32(pOdd ? v1 : v0);
                float v2 = __shfl_sync(0xffffffffu, s[kc][2], L0);
                float v3 = __shfl_sync(0xffffffffu, s[kc][3], L0);
                pa[1] = f2tf32(pOdd ? v3 : v2);
                v0 = __shfl_sync(0xffffffffu, s[kc][0], L1);
                v1 = __shfl_sync(0xffffffffu, s[kc][1], L1);
                pa[2] = f2tf32(pOdd ? v1 : v0);
                v2 = __shfl_sync(0xffffffffu, s[kc][2], L1);
                v3 = __shfl_sync(0xffffffffu, s[kc][3], L1);
                pa[3] = f2tf32(pOdd ? v3 : v2);
            }
            const uint32_t kk = ((((uint32_t)(kc << 1)) | cbit) ^ r7) << 4;
#pragma unroll
            for (int nt2 = 0; nt2 < 4; nt2++) {
                uint32_t bf[4];
                ldsm_x4(bf, vbuf + nt2 * 4096 + rterm + kk);
                mma_tf32(o[2 * nt2],     pa, bf[0], bf[1]);
                mma_tf32(o[2 * nt2 + 1], pa, bf[2], bf[3]);
            }
        }

        cur++; if (cur == 3) cur = 0;
    }

    /* ---- finalize: /l, tf32 bits for oproj cp.async ---- */
    const float inv0 = 1.f / l0s, inv1 = 1.f / l1s;
    const size_t row0 = (size_t)(b * SEQ + qt * 128 + w * 16 + r0);
#pragma unroll
    for (int nt = 0; nt < 8; nt++) {
        const int col = h * HDIM + nt * 8 + 2 * a4;
        *(float2*)&Out[row0 * HIDDEN + col] = make_float2(
            __uint_as_float(f2tf32(o[nt][0] * inv0)),
            __uint_as_float(f2tf32(o[nt][1] * inv0)));
        *(float2*)&Out[(row0 + 8) * HIDDEN + col] = make_float2(
            __uint_as_float(f2tf32(o[nt][2] * inv1)),
            __uint_as_float(f2tf32(o[nt][3] * inv1)));
    }
}

/* ================================================================= */
extern "C" void kernel_launch(void* const* d_in, const int* in_sizes, int n_in,
                              void* d_out, int out_size)
{
    (void)in_sizes; (void)n_in; (void)out_size;
    const float* x  = (const float*)d_in[0];
    /* d_in[1] = causal mask, handled analytically */
    const float* Wq = (const float*)d_in[2];
    const float* bq = (const float*)d_in[3];
    const float* Wk = (const float*)d_in[4];
    const float* bk = (const float*)d_in[5];
    const float* Wv = (const float*)d_in[6];
    const float* bv = (const float*)d_in[7];
    const float* Wo = (const float*)d_in[8];
    const float* bo = (const float*)d_in[9];
    float* out = (float*)d_out;

    float *q, *k, *vt, *attn;
    cudaGetSymbolAddress((void**)&q,    g_q);
    cudaGetSymbolAddress((void**)&k,    g_k);
    cudaGetSymbolAddress((void**)&vt,   g_vt);
    cudaGetSymbolAddress((void**)&attn, g_attn);

    cudaFuncSetAttribute(qkv_gemm,   cudaFuncAttributeMaxDynamicSharedMemorySize, GEMM_SMEM);
    cudaFuncSetAttribute(oproj_gemm, cudaFuncAttributeMaxDynamicSharedMemorySize, GEMM_SMEM);
    cudaFuncSetAttribute(attn_tc,    cudaFuncAttributeMaxDynamicSharedMemorySize, ATT_SMEM);

    /* 1. convert inputs to tf32 bits */
    cvt_all<<<2048, 256>>>((const float4*)x, (const float4*)Wq,
                           (const float4*)Wk, (const float4*)Wv,
                           (const float4*)Wo);

    /* 2. fused Q/K/V projection (K tf32, V tf32-transposed) */
    qkv_gemm<<<dim3(24, 16), 128, GEMM_SMEM>>>(bq, bk, bv);

    /* 3. causal GQA attention (cp.async staging, register P) */
    attn_tc<<<dim3(SEQ / 128, NHEADS, BATCH), 256, ATT_SMEM>>>(q, k, vt, attn);

    /* 4. output projection */
    oproj_gemm<<<dim3(16, 16), 128, GEMM_SMEM>>>(bo, out);
}